// round 1
// baseline (speedup 1.0000x reference)
#include <cuda_runtime.h>
#include <math.h>

// ---- problem dims ----
#define TT   2048      // tokens = B*S
#define HD   1024      // hidden
#define ID   2816      // expert intermediate
#define NE   8         // experts
#define ISD  1408      // shared intermediate

// ---- scratch (device globals; no allocation allowed) ----
__device__ int   g_count[NE];
__device__ int   g_tok[NE][TT];
__device__ int   g_slot[NE][TT];
__device__ float g_p[TT][2];
__device__ float g_act[(size_t)TT * 2 * ID];     // SwiGLU activations per (token,slot)
__device__ float g_dslot[(size_t)TT * 2 * HD];   // down-proj output per (token,slot)
__device__ float g_shact[(size_t)TT * ISD];      // shared-expert activations

__global__ void zero_counts_kernel() {
    if (threadIdx.x < NE) g_count[threadIdx.x] = 0;
}

// Router: logits -> top-2 -> softmax(2) -> push to per-expert lists
__global__ void router_kernel(const float* __restrict__ x,
                              const float* __restrict__ gw) {
    int t = blockIdx.x * blockDim.x + threadIdx.x;
    if (t >= TT) return;
    float lg[NE];
#pragma unroll
    for (int e = 0; e < NE; e++) lg[e] = 0.f;
    const float* xr = x + (size_t)t * HD;
    for (int h = 0; h < HD; h++) {
        float xv = xr[h];
#pragma unroll
        for (int e = 0; e < NE; e++) lg[e] = fmaf(xv, gw[h * NE + e], lg[e]);
    }
    int i0 = 0; float v0 = lg[0];
#pragma unroll
    for (int e = 1; e < NE; e++) if (lg[e] > v0) { v0 = lg[e]; i0 = e; }
    int i1 = -1; float v1 = -INFINITY;
#pragma unroll
    for (int e = 0; e < NE; e++) if (e != i0 && lg[e] > v1) { v1 = lg[e]; i1 = e; }
    float e1 = expf(v1 - v0);
    float inv = 1.f / (1.f + e1);
    g_p[t][0] = inv;
    g_p[t][1] = e1 * inv;
    int pos0 = atomicAdd(&g_count[i0], 1);
    g_tok[i0][pos0] = t; g_slot[i0][pos0] = 0;
    int pos1 = atomicAdd(&g_count[i1], 1);
    g_tok[i1][pos1] = t; g_slot[i1][pos1] = 1;
}

// ---- Grouped gate+up GEMM: act = silu(X@Wg[e]) * (X@Wu[e]) over gathered rows ----
// BM=BN=64, BK=16, 256 threads, 4x4 per-thread (x2 for g/u)
__global__ void expert_gateup_kernel(const float* __restrict__ x,
                                     const float* __restrict__ Wg,
                                     const float* __restrict__ Wu) {
    const int e   = blockIdx.z;
    const int cnt = g_count[e];
    const int m0  = blockIdx.x * 64;
    if (m0 >= cnt) return;
    const int n0  = blockIdx.y * 64;

    __shared__ float As[16][64];
    __shared__ float Bg[16][64];
    __shared__ float Bu[16][64];

    const int tid  = threadIdx.x;
    const int tx   = tid & 15, ty = tid >> 4;
    const int rowA = tid >> 2;
    const int kA   = (tid & 3) * 4;
    const int kB   = tid >> 4;
    const int nB   = (tid & 15) * 4;

    bool avalid = (m0 + rowA) < cnt;
    int tok = avalid ? g_tok[e][m0 + rowA] : 0;
    const float* xrow = x + (size_t)tok * HD;
    const float* pg = Wg + (size_t)e * HD * ID + n0;
    const float* pu = Wu + (size_t)e * HD * ID + n0;

    float ag[4][4] = {}; float au[4][4] = {};
    for (int k0 = 0; k0 < HD; k0 += 16) {
        float4 av = make_float4(0.f, 0.f, 0.f, 0.f);
        if (avalid) av = *(const float4*)(xrow + k0 + kA);
        As[kA + 0][rowA] = av.x; As[kA + 1][rowA] = av.y;
        As[kA + 2][rowA] = av.z; As[kA + 3][rowA] = av.w;
        *(float4*)&Bg[kB][nB] = *(const float4*)(pg + (size_t)(k0 + kB) * ID + nB);
        *(float4*)&Bu[kB][nB] = *(const float4*)(pu + (size_t)(k0 + kB) * ID + nB);
        __syncthreads();
#pragma unroll
        for (int kk = 0; kk < 16; kk++) {
            float4 a4  = *(const float4*)&As[kk][ty * 4];
            float4 bg4 = *(const float4*)&Bg[kk][tx * 4];
            float4 bu4 = *(const float4*)&Bu[kk][tx * 4];
            float aa[4]  = {a4.x, a4.y, a4.z, a4.w};
            float bgv[4] = {bg4.x, bg4.y, bg4.z, bg4.w};
            float buv[4] = {bu4.x, bu4.y, bu4.z, bu4.w};
#pragma unroll
            for (int i = 0; i < 4; i++)
#pragma unroll
                for (int j = 0; j < 4; j++) {
                    ag[i][j] = fmaf(aa[i], bgv[j], ag[i][j]);
                    au[i][j] = fmaf(aa[i], buv[j], au[i][j]);
                }
        }
        __syncthreads();
    }
#pragma unroll
    for (int i = 0; i < 4; i++) {
        int r = m0 + ty * 4 + i;
        if (r < cnt) {
            int flat = g_tok[e][r] * 2 + g_slot[e][r];
            float4 o;
            float* po = (float*)&o;
#pragma unroll
            for (int j = 0; j < 4; j++) {
                float g = ag[i][j], u = au[i][j];
                po[j] = u * g / (1.f + expf(-g));
            }
            *(float4*)(g_act + (size_t)flat * ID + n0 + tx * 4) = o;
        }
    }
}

// ---- Grouped down GEMM: dslot = act @ Wd[e] over gathered rows ----
__global__ void expert_down_kernel(const float* __restrict__ Wd) {
    const int e   = blockIdx.z;
    const int cnt = g_count[e];
    const int m0  = blockIdx.x * 64;
    if (m0 >= cnt) return;
    const int n0  = blockIdx.y * 64;

    __shared__ float As[16][64];
    __shared__ float Bs[16][64];

    const int tid  = threadIdx.x;
    const int tx   = tid & 15, ty = tid >> 4;
    const int rowA = tid >> 2;
    const int kA   = (tid & 3) * 4;
    const int kB   = tid >> 4;
    const int nB   = (tid & 15) * 4;

    bool avalid = (m0 + rowA) < cnt;
    const float* arow = g_act;  // base
    if (avalid) {
        int flat = g_tok[e][m0 + rowA] * 2 + g_slot[e][m0 + rowA];
        arow = g_act + (size_t)flat * ID;
    }
    const float* pb = Wd + (size_t)e * ID * HD + n0;

    float acc[4][4] = {};
    for (int k0 = 0; k0 < ID; k0 += 16) {
        float4 av = make_float4(0.f, 0.f, 0.f, 0.f);
        if (avalid) av = *(const float4*)(arow + k0 + kA);
        As[kA + 0][rowA] = av.x; As[kA + 1][rowA] = av.y;
        As[kA + 2][rowA] = av.z; As[kA + 3][rowA] = av.w;
        *(float4*)&Bs[kB][nB] = *(const float4*)(pb + (size_t)(k0 + kB) * HD + nB);
        __syncthreads();
#pragma unroll
        for (int kk = 0; kk < 16; kk++) {
            float4 a4 = *(const float4*)&As[kk][ty * 4];
            float4 b4 = *(const float4*)&Bs[kk][tx * 4];
            float aa[4] = {a4.x, a4.y, a4.z, a4.w};
            float bb[4] = {b4.x, b4.y, b4.z, b4.w};
#pragma unroll
            for (int i = 0; i < 4; i++)
#pragma unroll
                for (int j = 0; j < 4; j++)
                    acc[i][j] = fmaf(aa[i], bb[j], acc[i][j]);
        }
        __syncthreads();
    }
#pragma unroll
    for (int i = 0; i < 4; i++) {
        int r = m0 + ty * 4 + i;
        if (r < cnt) {
            int flat = g_tok[e][r] * 2 + g_slot[e][r];
            float4 o = make_float4(acc[i][0], acc[i][1], acc[i][2], acc[i][3]);
            *(float4*)(g_dslot + (size_t)flat * HD + n0 + tx * 4) = o;
        }
    }
}

// ---- Shared expert gate+up: g_shact = silu(X@Sg) * (X@Su) ----
__global__ void shared_gateup_kernel(const float* __restrict__ x,
                                     const float* __restrict__ Sg,
                                     const float* __restrict__ Su) {
    const int m0 = blockIdx.x * 64;
    const int n0 = blockIdx.y * 64;

    __shared__ float As[16][64];
    __shared__ float Bg[16][64];
    __shared__ float Bu[16][64];

    const int tid  = threadIdx.x;
    const int tx   = tid & 15, ty = tid >> 4;
    const int rowA = tid >> 2;
    const int kA   = (tid & 3) * 4;
    const int kB   = tid >> 4;
    const int nB   = (tid & 15) * 4;

    const float* xrow = x + (size_t)(m0 + rowA) * HD;
    const float* pg = Sg + n0;
    const float* pu = Su + n0;

    float ag[4][4] = {}; float au[4][4] = {};
    for (int k0 = 0; k0 < HD; k0 += 16) {
        float4 av = *(const float4*)(xrow + k0 + kA);
        As[kA + 0][rowA] = av.x; As[kA + 1][rowA] = av.y;
        As[kA + 2][rowA] = av.z; As[kA + 3][rowA] = av.w;
        *(float4*)&Bg[kB][nB] = *(const float4*)(pg + (size_t)(k0 + kB) * ISD + nB);
        *(float4*)&Bu[kB][nB] = *(const float4*)(pu + (size_t)(k0 + kB) * ISD + nB);
        __syncthreads();
#pragma unroll
        for (int kk = 0; kk < 16; kk++) {
            float4 a4  = *(const float4*)&As[kk][ty * 4];
            float4 bg4 = *(const float4*)&Bg[kk][tx * 4];
            float4 bu4 = *(const float4*)&Bu[kk][tx * 4];
            float aa[4]  = {a4.x, a4.y, a4.z, a4.w};
            float bgv[4] = {bg4.x, bg4.y, bg4.z, bg4.w};
            float buv[4] = {bu4.x, bu4.y, bu4.z, bu4.w};
#pragma unroll
            for (int i = 0; i < 4; i++)
#pragma unroll
                for (int j = 0; j < 4; j++) {
                    ag[i][j] = fmaf(aa[i], bgv[j], ag[i][j]);
                    au[i][j] = fmaf(aa[i], buv[j], au[i][j]);
                }
        }
        __syncthreads();
    }
#pragma unroll
    for (int i = 0; i < 4; i++) {
        int t = m0 + ty * 4 + i;
        float4 o;
        float* po = (float*)&o;
#pragma unroll
        for (int j = 0; j < 4; j++) {
            float g = ag[i][j], u = au[i][j];
            po[j] = u * g / (1.f + expf(-g));
        }
        *(float4*)(g_shact + (size_t)t * ISD + n0 + tx * 4) = o;
    }
}

// ---- Shared down GEMM fused with final combine:
//      out = g_shact @ Sd + p0*dslot[t,0] + p1*dslot[t,1] ----
__global__ void shared_down_combine_kernel(const float* __restrict__ Sd,
                                           float* __restrict__ out) {
    const int m0 = blockIdx.x * 64;
    const int n0 = blockIdx.y * 64;

    __shared__ float As[16][64];
    __shared__ float Bs[16][64];

    const int tid  = threadIdx.x;
    const int tx   = tid & 15, ty = tid >> 4;
    const int rowA = tid >> 2;
    const int kA   = (tid & 3) * 4;
    const int kB   = tid >> 4;
    const int nB   = (tid & 15) * 4;

    const float* arow = g_shact + (size_t)(m0 + rowA) * ISD;
    const float* pb = Sd + n0;

    float acc[4][4] = {};
    for (int k0 = 0; k0 < ISD; k0 += 16) {
        float4 av = *(const float4*)(arow + k0 + kA);
        As[kA + 0][rowA] = av.x; As[kA + 1][rowA] = av.y;
        As[kA + 2][rowA] = av.z; As[kA + 3][rowA] = av.w;
        *(float4*)&Bs[kB][nB] = *(const float4*)(pb + (size_t)(k0 + kB) * HD + nB);
        __syncthreads();
#pragma unroll
        for (int kk = 0; kk < 16; kk++) {
            float4 a4 = *(const float4*)&As[kk][ty * 4];
            float4 b4 = *(const float4*)&Bs[kk][tx * 4];
            float aa[4] = {a4.x, a4.y, a4.z, a4.w};
            float bb[4] = {b4.x, b4.y, b4.z, b4.w};
#pragma unroll
            for (int i = 0; i < 4; i++)
#pragma unroll
                for (int j = 0; j < 4; j++)
                    acc[i][j] = fmaf(aa[i], bb[j], acc[i][j]);
        }
        __syncthreads();
    }
#pragma unroll
    for (int i = 0; i < 4; i++) {
        int t = m0 + ty * 4 + i;
        float p0 = g_p[t][0];
        float p1 = g_p[t][1];
        const float* d0 = g_dslot + (size_t)(t * 2) * HD + n0 + tx * 4;
        const float* d1 = d0 + HD;
        float4 v0 = *(const float4*)d0;
        float4 v1 = *(const float4*)d1;
        float4 o;
        o.x = acc[i][0] + p0 * v0.x + p1 * v1.x;
        o.y = acc[i][1] + p0 * v0.y + p1 * v1.y;
        o.z = acc[i][2] + p0 * v0.z + p1 * v1.z;
        o.w = acc[i][3] + p0 * v0.w + p1 * v1.w;
        *(float4*)(out + (size_t)t * HD + n0 + tx * 4) = o;
    }
}

extern "C" void kernel_launch(void* const* d_in, const int* in_sizes, int n_in,
                              void* d_out, int out_size) {
    const float* x      = (const float*)d_in[0];  // [B,S,H]
    const float* gate_w = (const float*)d_in[1];  // [H,E]
    const float* Wg     = (const float*)d_in[2];  // [E,H,I]
    const float* Wu     = (const float*)d_in[3];  // [E,H,I]
    const float* Wd     = (const float*)d_in[4];  // [E,I,H]
    const float* Sg     = (const float*)d_in[5];  // [H,IS]
    const float* Su     = (const float*)d_in[6];  // [H,IS]
    const float* Sd     = (const float*)d_in[7];  // [IS,H]
    float* out = (float*)d_out;

    zero_counts_kernel<<<1, 32>>>();
    router_kernel<<<TT / 256, 256>>>(x, gate_w);

    dim3 gGU(TT / 64, ID / 64, NE);     // 32 x 44 x 8 (early-exit on count)
    expert_gateup_kernel<<<gGU, 256>>>(x, Wg, Wu);

    dim3 gD(TT / 64, HD / 64, NE);      // 32 x 16 x 8
    expert_down_kernel<<<gD, 256>>>(Wd);

    dim3 gSGU(TT / 64, ISD / 64);       // 32 x 22
    shared_gateup_kernel<<<gSGU, 256>>>(x, Sg, Su);

    dim3 gSD(TT / 64, HD / 64);         // 32 x 16
    shared_down_combine_kernel<<<gSD, 256>>>(Sd, out);
}